// round 14
// baseline (speedup 1.0000x reference)
#include <cuda_runtime.h>

#define SEQ   1025
#define SEQP  1088
#define NBLK  17
#define DM    768
#define DFF   3072
#define NH    12
#define HD    64
#define NLAY  12
#define NEGV  (-10000.0f)

// ---------------- scratch (no allocation allowed) ----------------
__device__ float g_patches[2*1024*DM];
__device__ float g_X   [2*SEQ *DM];
__device__ float g_xp  [2*SEQP*DM];
__device__ float g_Q   [2*SEQP*DM];
__device__ float g_K   [2*SEQP*DM];
__device__ float g_V   [2*SEQP*DM];
__device__ float g_ctx [2*SEQP*DM];
__device__ float g_xn2 [2*SEQ *DM];
__device__ float g_ffh [2*SEQ *DFF];

static inline int cdiv(int a, int b) { return (a + b - 1) / b; }

// ---------------- patch gather ----------------
__global__ void patch_gather(const float* __restrict__ px, float* __restrict__ out)
{
    int idx = blockIdx.x * blockDim.x + threadIdx.x;
    if (idx >= 2*1024*DM) return;
    int j  = idx % DM;
    int p  = (idx / DM) % 1024;
    int b  = idx / (DM * 1024);
    int c  = j >> 8;
    int py = (j >> 4) & 15;
    int pxl= j & 15;
    int gy = p >> 5;
    int gx = p & 31;
    out[idx] = px[(((size_t)b*3 + c)*512 + gy*16 + py)*512 + gx*16 + pxl];
}

// ---------------- embedding assemble ----------------
__global__ void assemble_embed(const float* __restrict__ tmp, const float* __restrict__ cls,
                               const float* __restrict__ pos, float* __restrict__ X)
{
    int idx = blockIdx.x * blockDim.x + threadIdx.x;
    if (idx >= 2*SEQ*DM) return;
    int d = idx % DM;
    int s = (idx / DM) % SEQ;
    int b = idx / (DM * SEQ);
    float v = (s == 0) ? cls[d] : tmp[((size_t)b*1024 + (s-1))*DM + d];
    X[idx] = v + pos[(size_t)s*DM + d];
}

// ---------------- layernorm (block per row), zero-pads rows >= rows_in ----------------
__global__ __launch_bounds__(256) void ln_kernel(const float* __restrict__ X,
                                                 const float* __restrict__ gam,
                                                 const float* __restrict__ bet,
                                                 float* __restrict__ Y,
                                                 int rows_in, int rows_out)
{
    __shared__ float redS[8];
    __shared__ float redQ[8];
    int r = blockIdx.x;
    int b = r / rows_out;
    int s = r % rows_out;
    int t = threadIdx.x;
    float* y = Y + (size_t)r * DM;
    if (s >= rows_in) {
        y[t] = 0.f; y[t+256] = 0.f; y[t+512] = 0.f;
        return;
    }
    const float* x = X + ((size_t)b*rows_in + s)*DM;
    float x0 = x[t], x1 = x[t+256], x2 = x[t+512];
    float sm = x0 + x1 + x2;
    float sq = x0*x0 + x1*x1 + x2*x2;
    #pragma unroll
    for (int o = 16; o > 0; o >>= 1) {
        sm += __shfl_xor_sync(0xffffffffu, sm, o);
        sq += __shfl_xor_sync(0xffffffffu, sq, o);
    }
    if ((t & 31) == 0) { redS[t >> 5] = sm; redQ[t >> 5] = sq; }
    __syncthreads();
    float ts = 0.f, tq = 0.f;
    #pragma unroll
    for (int w = 0; w < 8; w++) { ts += redS[w]; tq += redQ[w]; }
    float mean = ts * (1.f/768.f);
    float var  = tq * (1.f/768.f) - mean*mean;
    float inv  = rsqrtf(var + 1e-5f);
    y[t]     = (x0 - mean)*inv*gam[t]     + bet[t];
    y[t+256] = (x1 - mean)*inv*gam[t+256] + bet[t+256];
    y[t+512] = (x2 - mean)*inv*gam[t+512] + bet[t+512];
}

// ---------------- tf32 helpers ----------------
__device__ __forceinline__ unsigned f2tf(float x) {
    unsigned r;
    asm("cvt.rna.tf32.f32 %0, %1;" : "=r"(r) : "f"(x));
    return r;
}

__device__ __forceinline__ void mma_tf32(float* d, const unsigned* a, const unsigned* b) {
    asm volatile(
        "mma.sync.aligned.m16n8k8.row.col.f32.tf32.tf32.f32 "
        "{%0,%1,%2,%3}, {%4,%5,%6,%7}, {%8,%9}, {%0,%1,%2,%3};"
        : "+f"(d[0]), "+f"(d[1]), "+f"(d[2]), "+f"(d[3])
        : "r"(a[0]), "r"(a[1]), "r"(a[2]), "r"(a[3]), "r"(b[0]), "r"(b[1]));
}

// ---------------- tf32 tensor-core GEMM core (double-buffered, 128x128 tile) ----------------
// C[map(r), col0:col0+128] (+)= A[r, 0:K] @ W[K, col0:col0+128] + bias, per-CTA.
// flags: bit0=accumulate, bit1=GELU. Output row map: b = r / rows_in_pb,
// s = r % rows_in_pb; valid if s < rows_out_pb; out row = b*rows_out_pb + s.
// Tile: BM=128, BN=128, BK=16; 256 threads = 8 warps (2 M x 4 N), warp tile 64x32.
#define GBM 128
#define GBN 128
#define GAS 20    // As row stride (floats)
#define GBS 136   // Bs row stride (floats) -- 136 % 32 == 8 for perfect banks
#define ASZ (GBM*GAS)
#define BSZ (16*GBS)

__device__ __forceinline__ void gemm_body(const float* __restrict__ A,
                                          const float* __restrict__ W,
                                          const float* __restrict__ bias,
                                          float* __restrict__ C,
                                          int M, int N, int K, int flags,
                                          int rows_in_pb, int rows_out_pb,
                                          int row0, int col0,
                                          unsigned* As, unsigned* Bs)
{
    const int tid = threadIdx.x;
    const int w = tid >> 5, l = tid & 31;
    const int wm = w >> 2, wn = w & 3;        // 2 x 4 warp grid
    const int g = l >> 2, t = l & 3;

    // global load assignments
    const int arow = tid >> 1;           // 0..127
    const int acol = (tid & 1) * 8;      // 0 or 8
    const int brow = tid >> 4;           // 0..15
    const int bcol = (tid & 15) * 8;     // 0..120

    const int argl = row0 + arow;
    const bool avalid = argl < M;
    const float* Ap = avalid ? (A + (size_t)argl*K + acol) : A;
    const float* Wp = W + (size_t)brow*N + col0 + bcol;

    // prologue: load + store tile 0 into buffer 0
    float4 av0 = avalid ? *(const float4*)(Ap)     : make_float4(0.f,0.f,0.f,0.f);
    float4 av1 = avalid ? *(const float4*)(Ap + 4) : make_float4(0.f,0.f,0.f,0.f);
    float4 bv0 = *(const float4*)(Wp);
    float4 bv1 = *(const float4*)(Wp + 4);
    {
        uint4 u0 = make_uint4(f2tf(av0.x), f2tf(av0.y), f2tf(av0.z), f2tf(av0.w));
        uint4 u1 = make_uint4(f2tf(av1.x), f2tf(av1.y), f2tf(av1.z), f2tf(av1.w));
        *(uint4*)&As[arow*GAS + acol]     = u0;
        *(uint4*)&As[arow*GAS + acol + 4] = u1;
        uint4 w0 = make_uint4(f2tf(bv0.x), f2tf(bv0.y), f2tf(bv0.z), f2tf(bv0.w));
        uint4 w1 = make_uint4(f2tf(bv1.x), f2tf(bv1.y), f2tf(bv1.z), f2tf(bv1.w));
        *(uint4*)&Bs[brow*GBS + bcol]     = w0;
        *(uint4*)&Bs[brow*GBS + bcol + 4] = w1;
    }
    __syncthreads();

    float acc[4][4][4];
    #pragma unroll
    for (int mt = 0; mt < 4; mt++)
        #pragma unroll
        for (int nt = 0; nt < 4; nt++)
            #pragma unroll
            for (int i = 0; i < 4; i++) acc[mt][nt][i] = 0.f;

    int cur = 0;
    for (int k0 = 0; k0 < K; k0 += 16) {
        const bool more = (k0 + 16 < K);
        // issue next-tile global loads (latency hidden under MMAs)
        if (more) {
            av0 = avalid ? *(const float4*)(Ap + k0 + 16)     : make_float4(0.f,0.f,0.f,0.f);
            av1 = avalid ? *(const float4*)(Ap + k0 + 16 + 4) : make_float4(0.f,0.f,0.f,0.f);
            bv0 = *(const float4*)(Wp + (size_t)(k0 + 16)*N);
            bv1 = *(const float4*)(Wp + (size_t)(k0 + 16)*N + 4);
        }

        const unsigned* Ab = As + cur*ASZ;
        const unsigned* Bb = Bs + cur*BSZ;
        #pragma unroll
        for (int kh = 0; kh < 2; kh++) {
            const int kb = kh * 8;
            unsigned af[4][4], bf[4][2];
            #pragma unroll
            for (int mt = 0; mt < 4; mt++) {
                int r = wm*64 + mt*16;
                af[mt][0] = Ab[(r+g)  *GAS + kb + t];
                af[mt][1] = Ab[(r+g+8)*GAS + kb + t];
                af[mt][2] = Ab[(r+g)  *GAS + kb + t + 4];
                af[mt][3] = Ab[(r+g+8)*GAS + kb + t + 4];
            }
            #pragma unroll
            for (int nt = 0; nt < 4; nt++) {
                int c = wn*32 + nt*8 + g;
                bf[nt][0] = Bb[(kb+t)  *GBS + c];
                bf[nt][1] = Bb[(kb+t+4)*GBS + c];
            }
            #pragma unroll
            for (int mt = 0; mt < 4; mt++)
                #pragma unroll
                for (int nt = 0; nt < 4; nt++)
                    mma_tf32(acc[mt][nt], af[mt], bf[nt]);
        }

        if (more) {
            // store next tile into the other buffer; one barrier per step
            unsigned* An = As + (cur^1)*ASZ;
            unsigned* Bn = Bs + (cur^1)*BSZ;
            uint4 u0 = make_uint4(f2tf(av0.x), f2tf(av0.y), f2tf(av0.z), f2tf(av0.w));
            uint4 u1 = make_uint4(f2tf(av1.x), f2tf(av1.y), f2tf(av1.z), f2tf(av1.w));
            *(uint4*)&An[arow*GAS + acol]     = u0;
            *(uint4*)&An[arow*GAS + acol + 4] = u1;
            uint4 w0 = make_uint4(f2tf(bv0.x), f2tf(bv0.y), f2tf(bv0.z), f2tf(bv0.w));
            uint4 w1 = make_uint4(f2tf(bv1.x), f2tf(bv1.y), f2tf(bv1.z), f2tf(bv1.w));
            *(uint4*)&Bn[brow*GBS + bcol]     = w0;
            *(uint4*)&Bn[brow*GBS + bcol + 4] = w1;
            __syncthreads();
            cur ^= 1;
        }
    }

    // epilogue
    #pragma unroll
    for (int mt = 0; mt < 4; mt++) {
        #pragma unroll
        for (int half = 0; half < 2; half++) {
            int rl = wm*64 + mt*16 + g + half*8;
            int r  = row0 + rl;
            if (r < M) {
                int bidx = r / rows_in_pb;
                int s    = r - bidx * rows_in_pb;
                if (s < rows_out_pb) {
                    float* crow = C + ((size_t)bidx*rows_out_pb + s)*N + col0;
                    #pragma unroll
                    for (int nt = 0; nt < 4; nt++) {
                        int c = wn*32 + nt*8 + 2*t;
                        float v0 = acc[mt][nt][half*2+0] + bias[col0 + c];
                        float v1 = acc[mt][nt][half*2+1] + bias[col0 + c + 1];
                        if (flags & 2) {
                            v0 = 0.5f * v0 * (1.0f + erff(v0 * 0.70710678118654752f));
                            v1 = 0.5f * v1 * (1.0f + erff(v1 * 0.70710678118654752f));
                        }
                        if (flags & 1) {
                            float2 old = *(const float2*)(crow + c);
                            v0 += old.x; v1 += old.y;
                        }
                        *(float2*)(crow + c) = make_float2(v0, v1);
                    }
                }
            }
        }
    }
}

__global__ __launch_bounds__(256, 2) void gemm_tf32(const float* __restrict__ A,
                                                    const float* __restrict__ W,
                                                    const float* __restrict__ bias,
                                                    float* __restrict__ C,
                                                    int M, int N, int K, int flags,
                                                    int rows_in_pb, int rows_out_pb)
{
    __shared__ unsigned As[2*ASZ];
    __shared__ unsigned Bs[2*BSZ];
    gemm_body(A, W, bias, C, M, N, K, flags, rows_in_pb, rows_out_pb,
              blockIdx.y * GBM, blockIdx.x * GBN, As, Bs);
}

// merged QKV: grid.x = 3*(DM/GBN) = 18; sel picks the weight/bias/output set.
__global__ __launch_bounds__(256, 2) void gemm_qkv(const float* __restrict__ A,
                                                   const float* __restrict__ Wq,
                                                   const float* __restrict__ Wk,
                                                   const float* __restrict__ Wv,
                                                   const float* __restrict__ bq,
                                                   const float* __restrict__ bk,
                                                   const float* __restrict__ bv,
                                                   float* __restrict__ Q,
                                                   float* __restrict__ Kout,
                                                   float* __restrict__ V,
                                                   int M, int Kdim)
{
    __shared__ unsigned As[2*ASZ];
    __shared__ unsigned Bs[2*BSZ];
    const int blocks_per = DM / GBN;      // 6
    const int sel  = blockIdx.x / blocks_per;
    const int col0 = (blockIdx.x - sel * blocks_per) * GBN;
    const float* W = (sel == 0) ? Wq : (sel == 1) ? Wk : Wv;
    const float* b = (sel == 0) ? bq : (sel == 1) ? bk : bv;
    float*       C = (sel == 0) ? Q  : (sel == 1) ? Kout : V;
    gemm_body(A, W, b, C, M, DM, Kdim, 0, M, M,
              blockIdx.y * GBM, col0, As, Bs);
}

// ---------------- BigBird sparse attention (fp32, online softmax) ----------------
__global__ __launch_bounds__(256) void attn_kernel(const float* __restrict__ Qg,
                                                   const float* __restrict__ Kg,
                                                   const float* __restrict__ Vg,
                                                   const int*   __restrict__ rnd,
                                                   float* __restrict__ ctx)
{
    extern __shared__ float smem[];
    float* Qs = smem;              // 64 x 65
    float* Ks = smem + 64*65;
    float* Vs = smem + 2*64*65;
    float* Ps = smem + 3*64*65;

    const int qb  = blockIdx.x;
    const int h   = blockIdx.y;
    const int b   = blockIdx.z;
    const int tid = threadIdx.x;
    const int ty  = tid >> 4;
    const int tx  = tid & 15;

    int blist[17];
    int nb;
    if (qb == 0 || qb == NBLK-1) {
        nb = NBLK;
        #pragma unroll
        for (int i = 0; i < NBLK; i++) blist[i] = i;
    } else {
        const int* rp = rnd + ((size_t)h*15 + (qb-1))*3;
        int r0 = rp[0], r1 = rp[1], r2 = rp[2];
        if (qb == 1) {
            blist[0]=0; blist[1]=1; blist[2]=2; blist[3]=16;
            blist[4]=r0; blist[5]=r1; blist[6]=r2; nb = 7;
        } else if (qb == 15) {
            blist[0]=0; blist[1]=14; blist[2]=15; blist[3]=16;
            blist[4]=r0; blist[5]=r1; blist[6]=r2; nb = 7;
        } else {
            blist[0]=0; blist[1]=qb-1; blist[2]=qb; blist[3]=qb+1;
            blist[4]=r0; blist[5]=r1; blist[6]=r2; blist[7]=16; nb = 8;
        }
    }

    const float* qbase = Qg + ((size_t)(b*SEQP + qb*64))*DM + h*HD;
    #pragma unroll
    for (int it = 0; it < 4; it++) {
        int e = it*256 + tid;
        int row = e >> 4, c4 = (e & 15)*4;
        float4 v = *(const float4*)(qbase + (size_t)row*DM + c4);
        Qs[row*65 + c4 + 0] = v.x * 0.125f;
        Qs[row*65 + c4 + 1] = v.y * 0.125f;
        Qs[row*65 + c4 + 2] = v.z * 0.125f;
        Qs[row*65 + c4 + 3] = v.w * 0.125f;
    }

    float Mr[4], Lr[4], acc[4][4];
    #pragma unroll
    for (int i = 0; i < 4; i++) {
        Mr[i] = -1e30f; Lr[i] = 0.f;
        #pragma unroll
        for (int j = 0; j < 4; j++) acc[i][j] = 0.f;
    }

    for (int bi = 0; bi < nb; bi++) {
        int kb = blist[bi];
        const float* kbase = Kg + ((size_t)(b*SEQP + kb*64))*DM + h*HD;
        const float* vbase = Vg + ((size_t)(b*SEQP + kb*64))*DM + h*HD;
        __syncthreads();
        #pragma unroll
        for (int it = 0; it < 4; it++) {
            int e = it*256 + tid;
            int row = e >> 4, c4 = (e & 15)*4;
            float4 kv = *(const float4*)(kbase + (size_t)row*DM + c4);
            float4 vv = *(const float4*)(vbase + (size_t)row*DM + c4);
            Ks[row*65 + c4 + 0] = kv.x; Ks[row*65 + c4 + 1] = kv.y;
            Ks[row*65 + c4 + 2] = kv.z; Ks[row*65 + c4 + 3] = kv.w;
            Vs[row*65 + c4 + 0] = vv.x; Vs[row*65 + c4 + 1] = vv.y;
            Vs[row*65 + c4 + 2] = vv.z; Vs[row*65 + c4 + 3] = vv.w;
        }
        __syncthreads();

        float s[4][4];
        #pragma unroll
        for (int i = 0; i < 4; i++)
            #pragma unroll
            for (int j = 0; j < 4; j++) s[i][j] = 0.f;
        #pragma unroll 16
        for (int d = 0; d < 64; d++) {
            float a0 = Qs[(ty*4+0)*65 + d];
            float a1 = Qs[(ty*4+1)*65 + d];
            float a2 = Qs[(ty*4+2)*65 + d];
            float a3 = Qs[(ty*4+3)*65 + d];
            float k0 = Ks[(tx*4+0)*65 + d];
            float k1 = Ks[(tx*4+1)*65 + d];
            float k2 = Ks[(tx*4+2)*65 + d];
            float k3 = Ks[(tx*4+3)*65 + d];
            s[0][0] += a0*k0; s[0][1] += a0*k1; s[0][2] += a0*k2; s[0][3] += a0*k3;
            s[1][0] += a1*k0; s[1][1] += a1*k1; s[1][2] += a1*k2; s[1][3] += a1*k3;
            s[2][0] += a2*k0; s[2][1] += a2*k1; s[2][2] += a2*k2; s[2][3] += a2*k3;
            s[3][0] += a3*k0; s[3][1] += a3*k1; s[3][2] += a3*k2; s[3][3] += a3*k3;
        }
        int kst = kb*64 + tx*4;
        #pragma unroll
        for (int j = 0; j < 4; j++) {
            if (kst + j >= SEQ) {
                #pragma unroll
                for (int i = 0; i < 4; i++) s[i][j] += NEGV;
            }
        }
        float al[4];
        #pragma unroll
        for (int i = 0; i < 4; i++) {
            float m = fmaxf(fmaxf(s[i][0], s[i][1]), fmaxf(s[i][2], s[i][3]));
            #pragma unroll
            for (int o = 8; o > 0; o >>= 1)
                m = fmaxf(m, __shfl_xor_sync(0xffffffffu, m, o));
            float nm = fmaxf(Mr[i], m);
            al[i] = expf(Mr[i] - nm);
            Mr[i] = nm;
            float rsum = 0.f;
            #pragma unroll
            for (int j = 0; j < 4; j++) {
                float p = expf(s[i][j] - nm);
                Ps[(ty*4+i)*65 + tx*4 + j] = p;
                rsum += p;
            }
            #pragma unroll
            for (int o = 8; o > 0; o >>= 1)
                rsum += __shfl_xor_sync(0xffffffffu, rsum, o);
            Lr[i] = Lr[i]*al[i] + rsum;
        }
        __syncthreads();
        #pragma unroll
        for (int i = 0; i < 4; i++)
            #pragma unroll
            for (int j = 0; j < 4; j++) acc[i][j] *= al[i];
        #pragma unroll 16
        for (int k = 0; k < 64; k++) {
            float p0 = Ps[(ty*4+0)*65 + k];
            float p1 = Ps[(ty*4+1)*65 + k];
            float p2 = Ps[(ty*4+2)*65 + k];
            float p3 = Ps[(ty*4+3)*65 + k];
            float v0 = Vs[k*65 + tx*4 + 0];
            float v1 = Vs[k*65 + tx*4 + 1];
            float v2 = Vs[k*65 + tx*4 + 2];
            float v3 = Vs[k*65 + tx*4 + 3];
            acc[0][0] += p0*v0; acc[0][1] += p0*v1; acc[0][2] += p0*v2; acc[0][3] += p0*v3;
            acc[1][0] += p1*v0; acc[1][1] += p1*v1; acc[1][2] += p1*v2; acc[1][3] += p1*v3;
            acc[2][0] += p2*v0; acc[2][1] += p2*v1; acc[2][2] += p2*v2; acc[2][3] += p2*v3;
            acc[3][0] += p3*v0; acc[3][1] += p3*v1; acc[3][2] += p3*v2; acc[3][3] += p3*v3;
        }
    }

    float* obase = ctx + ((size_t)(b*SEQP + qb*64))*DM + h*HD;
    #pragma unroll
    for (int i = 0; i < 4; i++) {
        float inv = 1.f / Lr[i];
        *(float4*)(obase + (size_t)(ty*4+i)*DM + tx*4) =
            make_float4(acc[i][0]*inv, acc[i][1]*inv, acc[i][2]*inv, acc[i][3]*inv);
    }
}

// ---------------- host orchestration ----------------
extern "C" void kernel_launch(void* const* d_in, const int* in_sizes, int n_in,
                              void* d_out, int out_size)
{
    const float* pixel   = (const float*)d_in[0];
    const float* patch_w = (const float*)d_in[1];
    const float* patch_b = (const float*)d_in[2];
    const float* cls     = (const float*)d_in[3];
    const float* pos     = (const float*)d_in[4];
    const float* Wq      = (const float*)d_in[5];
    const float* bq      = (const float*)d_in[6];
    const float* Wk      = (const float*)d_in[7];
    const float* bk      = (const float*)d_in[8];
    const float* Wv      = (const float*)d_in[9];
    const float* bv      = (const float*)d_in[10];
    const float* Wo      = (const float*)d_in[11];
    const float* bo      = (const float*)d_in[12];
    const float* ln1g    = (const float*)d_in[13];
    const float* ln1b    = (const float*)d_in[14];
    const float* ln2g    = (const float*)d_in[15];
    const float* ln2b    = (const float*)d_in[16];
    const float* fw1     = (const float*)d_in[17];
    const float* fb1     = (const float*)d_in[18];
    const float* fw2     = (const float*)d_in[19];
    const float* fb2     = (const float*)d_in[20];
    const float* ng      = (const float*)d_in[21];
    const float* nbias   = (const float*)d_in[22];
    const int*   rnd     = (const int*)d_in[23];
    float* out = (float*)d_out;

    float *pPatch, *pX, *pXp, *pQ, *pK, *pV, *pCtx, *pXn2, *pFfh;
    cudaGetSymbolAddress((void**)&pPatch, g_patches);
    cudaGetSymbolAddress((void**)&pX,   g_X);
    cudaGetSymbolAddress((void**)&pXp,  g_xp);
    cudaGetSymbolAddress((void**)&pQ,   g_Q);
    cudaGetSymbolAddress((void**)&pK,   g_K);
    cudaGetSymbolAddress((void**)&pV,   g_V);
    cudaGetSymbolAddress((void**)&pCtx, g_ctx);
    cudaGetSymbolAddress((void**)&pXn2, g_xn2);
    cudaGetSymbolAddress((void**)&pFfh, g_ffh);

    const int attn_smem = 4*64*65*(int)sizeof(float);  // 66560 B
    cudaFuncSetAttribute(attn_kernel, cudaFuncAttributeMaxDynamicSharedMemorySize, attn_smem);

    // ---- patch embedding ----
    patch_gather<<<cdiv(2*1024*DM, 256), 256>>>(pixel, pPatch);
    gemm_tf32<<<dim3(DM/GBN, cdiv(2048, GBM)), 256>>>(pPatch, patch_w, patch_b, pCtx,
                                                      2048, DM, DM, 0, 2048, 2048);
    assemble_embed<<<cdiv(2*SEQ*DM, 256), 256>>>(pCtx, cls, pos, pX);

    for (int l = 0; l < NLAY; l++) {
        const size_t wo = (size_t)l*DM*DM;
        // LN1 -> padded (zeros in pad rows)
        ln_kernel<<<2*SEQP, 256>>>(pX, ln1g + l*DM, ln1b + l*DM, pXp, SEQ, SEQP);
        // merged QKV projection (tf32 MMA), 306 CTAs
        gemm_qkv<<<dim3(3*DM/GBN, cdiv(2*SEQP, GBM)), 256>>>(pXp,
                                                             Wq + wo, Wk + wo, Wv + wo,
                                                             bq + l*DM, bk + l*DM, bv + l*DM,
                                                             pQ, pK, pV, 2*SEQP, DM);
        // sparse attention (fp32)
        attn_kernel<<<dim3(NBLK, NH, 2), 256, attn_smem>>>(pQ, pK, pV, rnd, pCtx);
        // output projection: single launch over both batches, row-remapped accumulate
        gemm_tf32<<<dim3(DM/GBN, cdiv(2*SEQP, GBM)), 256>>>(pCtx, Wo + wo, bo + l*DM, pX,
                                                            2*SEQP, DM, DM, 1, SEQP, SEQ);
        // LN2 + FFN
        ln_kernel<<<2*SEQ, 256>>>(pX, ln2g + l*DM, ln2b + l*DM, pXn2, SEQ, SEQ);
        gemm_tf32<<<dim3(DFF/GBN, cdiv(2*SEQ, GBM)), 256>>>(pXn2, fw1 + (size_t)l*DM*DFF,
                                                            fb1 + l*DFF, pFfh,
                                                            2*SEQ, DFF, DM, 2, 2*SEQ, 2*SEQ);
        gemm_tf32<<<dim3(DM/GBN, cdiv(2*SEQ, GBM)), 256>>>(pFfh, fw2 + (size_t)l*DFF*DM,
                                                           fb2 + l*DM, pX,
                                                           2*SEQ, DM, DFF, 1, 2*SEQ, 2*SEQ);
    }
    // final layernorm straight into d_out
    ln_kernel<<<2*SEQ, 256>>>(pX, ng, nbias, out, SEQ, SEQ);
}

// round 15
// speedup vs baseline: 1.0258x; 1.0258x over previous
#include <cuda_runtime.h>

#define SEQ   1025
#define SEQP  1088
#define NBLK  17
#define DM    768
#define DFF   3072
#define NH    12
#define HD    64
#define NLAY  12
#define NEGV  (-10000.0f)

// ---------------- scratch (no allocation allowed) ----------------
__device__ float g_patches[2*1024*DM];
__device__ float g_X   [2*SEQ *DM];
__device__ float g_xp  [2*SEQP*DM];
__device__ float g_Q   [2*SEQP*DM];
__device__ float g_K   [2*SEQP*DM];
__device__ float g_V   [2*SEQP*DM];
__device__ float g_ctx [2*SEQP*DM];
__device__ float g_xn2 [2*SEQ *DM];
__device__ float g_ffh [2*SEQ *DFF];

static inline int cdiv(int a, int b) { return (a + b - 1) / b; }

// ---------------- patch gather ----------------
__global__ void patch_gather(const float* __restrict__ px, float* __restrict__ out)
{
    int idx = blockIdx.x * blockDim.x + threadIdx.x;
    if (idx >= 2*1024*DM) return;
    int j  = idx % DM;
    int p  = (idx / DM) % 1024;
    int b  = idx / (DM * 1024);
    int c  = j >> 8;
    int py = (j >> 4) & 15;
    int pxl= j & 15;
    int gy = p >> 5;
    int gx = p & 31;
    out[idx] = px[(((size_t)b*3 + c)*512 + gy*16 + py)*512 + gx*16 + pxl];
}

// ---------------- embedding assemble ----------------
__global__ void assemble_embed(const float* __restrict__ tmp, const float* __restrict__ cls,
                               const float* __restrict__ pos, float* __restrict__ X)
{
    int idx = blockIdx.x * blockDim.x + threadIdx.x;
    if (idx >= 2*SEQ*DM) return;
    int d = idx % DM;
    int s = (idx / DM) % SEQ;
    int b = idx / (DM * SEQ);
    float v = (s == 0) ? cls[d] : tmp[((size_t)b*1024 + (s-1))*DM + d];
    X[idx] = v + pos[(size_t)s*DM + d];
}

// ---------------- layernorm (block per row), zero-pads rows >= rows_in ----------------
__global__ __launch_bounds__(256) void ln_kernel(const float* __restrict__ X,
                                                 const float* __restrict__ gam,
                                                 const float* __restrict__ bet,
                                                 float* __restrict__ Y,
                                                 int rows_in, int rows_out)
{
    __shared__ float redS[8];
    __shared__ float redQ[8];
    int r = blockIdx.x;
    int b = r / rows_out;
    int s = r % rows_out;
    int t = threadIdx.x;
    float* y = Y + (size_t)r * DM;
    if (s >= rows_in) {
        y[t] = 0.f; y[t+256] = 0.f; y[t+512] = 0.f;
        return;
    }
    const float* x = X + ((size_t)b*rows_in + s)*DM;
    float x0 = x[t], x1 = x[t+256], x2 = x[t+512];
    float sm = x0 + x1 + x2;
    float sq = x0*x0 + x1*x1 + x2*x2;
    #pragma unroll
    for (int o = 16; o > 0; o >>= 1) {
        sm += __shfl_xor_sync(0xffffffffu, sm, o);
        sq += __shfl_xor_sync(0xffffffffu, sq, o);
    }
    if ((t & 31) == 0) { redS[t >> 5] = sm; redQ[t >> 5] = sq; }
    __syncthreads();
    float ts = 0.f, tq = 0.f;
    #pragma unroll
    for (int w = 0; w < 8; w++) { ts += redS[w]; tq += redQ[w]; }
    float mean = ts * (1.f/768.f);
    float var  = tq * (1.f/768.f) - mean*mean;
    float inv  = rsqrtf(var + 1e-5f);
    y[t]     = (x0 - mean)*inv*gam[t]     + bet[t];
    y[t+256] = (x1 - mean)*inv*gam[t+256] + bet[t+256];
    y[t+512] = (x2 - mean)*inv*gam[t+512] + bet[t+512];
}

// ---------------- tf32 helpers ----------------
__device__ __forceinline__ unsigned f2tf(float x) {
    unsigned r;
    asm("cvt.rna.tf32.f32 %0, %1;" : "=r"(r) : "f"(x));
    return r;
}

__device__ __forceinline__ void mma_tf32(float* d, const unsigned* a, const unsigned* b) {
    asm volatile(
        "mma.sync.aligned.m16n8k8.row.col.f32.tf32.tf32.f32 "
        "{%0,%1,%2,%3}, {%4,%5,%6,%7}, {%8,%9}, {%0,%1,%2,%3};"
        : "+f"(d[0]), "+f"(d[1]), "+f"(d[2]), "+f"(d[3])
        : "r"(a[0]), "r"(a[1]), "r"(a[2]), "r"(a[3]), "r"(b[0]), "r"(b[1]));
}

// ---------------- tf32 tensor-core GEMM core (double-buffered, 128x128 tile) ----------------
#define GBM 128
#define GBN 128
#define GAS 20    // As row stride (floats)
#define GBS 136   // Bs row stride (floats) -- 136 % 32 == 8 for perfect banks
#define ASZ (GBM*GAS)
#define BSZ (16*GBS)

__device__ __forceinline__ void gemm_body(const float* __restrict__ A,
                                          const float* __restrict__ W,
                                          const float* __restrict__ bias,
                                          float* __restrict__ C,
                                          int M, int N, int K, int flags,
                                          int rows_in_pb, int rows_out_pb,
                                          int row0, int col0,
                                          unsigned* As, unsigned* Bs)
{
    const int tid = threadIdx.x;
    const int w = tid >> 5, l = tid & 31;
    const int wm = w >> 2, wn = w & 3;        // 2 x 4 warp grid
    const int g = l >> 2, t = l & 3;

    const int arow = tid >> 1;           // 0..127
    const int acol = (tid & 1) * 8;      // 0 or 8
    const int brow = tid >> 4;           // 0..15
    const int bcol = (tid & 15) * 8;     // 0..120

    const int argl = row0 + arow;
    const bool avalid = argl < M;
    const float* Ap = avalid ? (A + (size_t)argl*K + acol) : A;
    const float* Wp = W + (size_t)brow*N + col0 + bcol;

    float4 av0 = avalid ? *(const float4*)(Ap)     : make_float4(0.f,0.f,0.f,0.f);
    float4 av1 = avalid ? *(const float4*)(Ap + 4) : make_float4(0.f,0.f,0.f,0.f);
    float4 bv0 = *(const float4*)(Wp);
    float4 bv1 = *(const float4*)(Wp + 4);
    {
        uint4 u0 = make_uint4(f2tf(av0.x), f2tf(av0.y), f2tf(av0.z), f2tf(av0.w));
        uint4 u1 = make_uint4(f2tf(av1.x), f2tf(av1.y), f2tf(av1.z), f2tf(av1.w));
        *(uint4*)&As[arow*GAS + acol]     = u0;
        *(uint4*)&As[arow*GAS + acol + 4] = u1;
        uint4 w0 = make_uint4(f2tf(bv0.x), f2tf(bv0.y), f2tf(bv0.z), f2tf(bv0.w));
        uint4 w1 = make_uint4(f2tf(bv1.x), f2tf(bv1.y), f2tf(bv1.z), f2tf(bv1.w));
        *(uint4*)&Bs[brow*GBS + bcol]     = w0;
        *(uint4*)&Bs[brow*GBS + bcol + 4] = w1;
    }
    __syncthreads();

    float acc[4][4][4];
    #pragma unroll
    for (int mt = 0; mt < 4; mt++)
        #pragma unroll
        for (int nt = 0; nt < 4; nt++)
            #pragma unroll
            for (int i = 0; i < 4; i++) acc[mt][nt][i] = 0.f;

    int cur = 0;
    for (int k0 = 0; k0 < K; k0 += 16) {
        const bool more = (k0 + 16 < K);
        if (more) {
            av0 = avalid ? *(const float4*)(Ap + k0 + 16)     : make_float4(0.f,0.f,0.f,0.f);
            av1 = avalid ? *(const float4*)(Ap + k0 + 16 + 4) : make_float4(0.f,0.f,0.f,0.f);
            bv0 = *(const float4*)(Wp + (size_t)(k0 + 16)*N);
            bv1 = *(const float4*)(Wp + (size_t)(k0 + 16)*N + 4);
        }

        const unsigned* Ab = As + cur*ASZ;
        const unsigned* Bb = Bs + cur*BSZ;
        #pragma unroll
        for (int kh = 0; kh < 2; kh++) {
            const int kb = kh * 8;
            unsigned af[4][4], bf[4][2];
            #pragma unroll
            for (int mt = 0; mt < 4; mt++) {
                int r = wm*64 + mt*16;
                af[mt][0] = Ab[(r+g)  *GAS + kb + t];
                af[mt][1] = Ab[(r+g+8)*GAS + kb + t];
                af[mt][2] = Ab[(r+g)  *GAS + kb + t + 4];
                af[mt][3] = Ab[(r+g+8)*GAS + kb + t + 4];
            }
            #pragma unroll
            for (int nt = 0; nt < 4; nt++) {
                int c = wn*32 + nt*8 + g;
                bf[nt][0] = Bb[(kb+t)  *GBS + c];
                bf[nt][1] = Bb[(kb+t+4)*GBS + c];
            }
            #pragma unroll
            for (int mt = 0; mt < 4; mt++)
                #pragma unroll
                for (int nt = 0; nt < 4; nt++)
                    mma_tf32(acc[mt][nt], af[mt], bf[nt]);
        }

        if (more) {
            unsigned* An = As + (cur^1)*ASZ;
            unsigned* Bn = Bs + (cur^1)*BSZ;
            uint4 u0 = make_uint4(f2tf(av0.x), f2tf(av0.y), f2tf(av0.z), f2tf(av0.w));
            uint4 u1 = make_uint4(f2tf(av1.x), f2tf(av1.y), f2tf(av1.z), f2tf(av1.w));
            *(uint4*)&An[arow*GAS + acol]     = u0;
            *(uint4*)&An[arow*GAS + acol + 4] = u1;
            uint4 w0 = make_uint4(f2tf(bv0.x), f2tf(bv0.y), f2tf(bv0.z), f2tf(bv0.w));
            uint4 w1 = make_uint4(f2tf(bv1.x), f2tf(bv1.y), f2tf(bv1.z), f2tf(bv1.w));
            *(uint4*)&Bn[brow*GBS + bcol]     = w0;
            *(uint4*)&Bn[brow*GBS + bcol + 4] = w1;
            __syncthreads();
            cur ^= 1;
        }
    }

    // epilogue
    #pragma unroll
    for (int mt = 0; mt < 4; mt++) {
        #pragma unroll
        for (int half = 0; half < 2; half++) {
            int rl = wm*64 + mt*16 + g + half*8;
            int r  = row0 + rl;
            if (r < M) {
                int bidx = r / rows_in_pb;
                int s    = r - bidx * rows_in_pb;
                if (s < rows_out_pb) {
                    float* crow = C + ((size_t)bidx*rows_out_pb + s)*N + col0;
                    #pragma unroll
                    for (int nt = 0; nt < 4; nt++) {
                        int c = wn*32 + nt*8 + 2*t;
                        float v0 = acc[mt][nt][half*2+0] + bias[col0 + c];
                        float v1 = acc[mt][nt][half*2+1] + bias[col0 + c + 1];
                        if (flags & 2) {
                            v0 = 0.5f * v0 * (1.0f + erff(v0 * 0.70710678118654752f));
                            v1 = 0.5f * v1 * (1.0f + erff(v1 * 0.70710678118654752f));
                        }
                        if (flags & 1) {
                            float2 old = *(const float2*)(crow + c);
                            v0 += old.x; v1 += old.y;
                        }
                        *(float2*)(crow + c) = make_float2(v0, v1);
                    }
                }
            }
        }
    }
}

__global__ __launch_bounds__(256, 2) void gemm_tf32(const float* __restrict__ A,
                                                    const float* __restrict__ W,
                                                    const float* __restrict__ bias,
                                                    float* __restrict__ C,
                                                    int M, int N, int K, int flags,
                                                    int rows_in_pb, int rows_out_pb)
{
    __shared__ unsigned As[2*ASZ];
    __shared__ unsigned Bs[2*BSZ];
    gemm_body(A, W, bias, C, M, N, K, flags, rows_in_pb, rows_out_pb,
              blockIdx.y * GBM, blockIdx.x * GBN, As, Bs);
}

// merged QKV: grid.x = 3*(DM/GBN) = 18; sel picks the weight/bias/output set.
__global__ __launch_bounds__(256, 2) void gemm_qkv(const float* __restrict__ A,
                                                   const float* __restrict__ Wq,
                                                   const float* __restrict__ Wk,
                                                   const float* __restrict__ Wv,
                                                   const float* __restrict__ bq,
                                                   const float* __restrict__ bk,
                                                   const float* __restrict__ bv,
                                                   float* __restrict__ Q,
                                                   float* __restrict__ Kout,
                                                   float* __restrict__ V,
                                                   int M, int Kdim)
{
    __shared__ unsigned As[2*ASZ];
    __shared__ unsigned Bs[2*BSZ];
    const int blocks_per = DM / GBN;      // 6
    const int sel  = blockIdx.x / blocks_per;
    const int col0 = (blockIdx.x - sel * blocks_per) * GBN;
    const float* W = (sel == 0) ? Wq : (sel == 1) ? Wk : Wv;
    const float* b = (sel == 0) ? bq : (sel == 1) ? bk : bv;
    float*       C = (sel == 0) ? Q  : (sel == 1) ? Kout : V;
    gemm_body(A, W, b, C, M, DM, Kdim, 0, M, M,
              blockIdx.y * GBM, col0, As, Bs);
}

// ---------------- BigBird sparse attention (fp32, online softmax) ----------------
// Vectorized smem: Q[row][d] s68, KT[d][key] s68 (transposed), V[k][d] s68,
// P[row][k] s68. All inner-loop smem traffic is LDS.128 / STS.128, conflict-free.
#define ATS 68
__global__ __launch_bounds__(256) void attn_kernel(const float* __restrict__ Qg,
                                                   const float* __restrict__ Kg,
                                                   const float* __restrict__ Vg,
                                                   const int*   __restrict__ rnd,
                                                   float* __restrict__ ctx)
{
    extern __shared__ float smem[];
    float* Qs = smem;               // 64 x 68 (row, d)
    float* KT = smem + 64*ATS;      // 64 x 68 (d, key)  -- transposed
    float* Vs = smem + 2*64*ATS;    // 64 x 68 (k, d)
    float* Ps = smem + 3*64*ATS;    // 64 x 68 (row, k)

    const int qb  = blockIdx.x;
    const int h   = blockIdx.y;
    const int b   = blockIdx.z;
    const int tid = threadIdx.x;
    const int ty  = tid >> 4;
    const int tx  = tid & 15;

    int blist[17];
    int nb;
    if (qb == 0 || qb == NBLK-1) {
        nb = NBLK;
        #pragma unroll
        for (int i = 0; i < NBLK; i++) blist[i] = i;
    } else {
        const int* rp = rnd + ((size_t)h*15 + (qb-1))*3;
        int r0 = rp[0], r1 = rp[1], r2 = rp[2];
        if (qb == 1) {
            blist[0]=0; blist[1]=1; blist[2]=2; blist[3]=16;
            blist[4]=r0; blist[5]=r1; blist[6]=r2; nb = 7;
        } else if (qb == 15) {
            blist[0]=0; blist[1]=14; blist[2]=15; blist[3]=16;
            blist[4]=r0; blist[5]=r1; blist[6]=r2; nb = 7;
        } else {
            blist[0]=0; blist[1]=qb-1; blist[2]=qb; blist[3]=qb+1;
            blist[4]=r0; blist[5]=r1; blist[6]=r2; blist[7]=16; nb = 8;
        }
    }

    // load Q tile, pre-scaled by 1/sqrt(64)
    const float* qbase = Qg + ((size_t)(b*SEQP + qb*64))*DM + h*HD;
    #pragma unroll
    for (int it = 0; it < 4; it++) {
        int e = it*256 + tid;
        int row = e >> 4, c4 = (e & 15)*4;
        float4 v = *(const float4*)(qbase + (size_t)row*DM + c4);
        *(float4*)&Qs[row*ATS + c4] =
            make_float4(v.x*0.125f, v.y*0.125f, v.z*0.125f, v.w*0.125f);
    }

    float Mr[4], Lr[4], acc[4][4];
    #pragma unroll
    for (int i = 0; i < 4; i++) {
        Mr[i] = -1e30f; Lr[i] = 0.f;
        #pragma unroll
        for (int j = 0; j < 4; j++) acc[i][j] = 0.f;
    }

    for (int bi = 0; bi < nb; bi++) {
        int kb = blist[bi];
        const float* kbase = Kg + ((size_t)(b*SEQP + kb*64))*DM + h*HD;
        const float* vbase = Vg + ((size_t)(b*SEQP + kb*64))*DM + h*HD;
        __syncthreads();   // previous iter done reading KT/Vs/Ps; iter0: Qs stores done
        #pragma unroll
        for (int it = 0; it < 4; it++) {
            int e = it*256 + tid;
            int row = e >> 4, c4 = (e & 15)*4;   // row = key index, c4 = d quad
            float4 kv = *(const float4*)(kbase + (size_t)row*DM + c4);
            float4 vv = *(const float4*)(vbase + (size_t)row*DM + c4);
            // K transposed: KT[d][key]
            KT[(c4+0)*ATS + row] = kv.x;
            KT[(c4+1)*ATS + row] = kv.y;
            KT[(c4+2)*ATS + row] = kv.z;
            KT[(c4+3)*ATS + row] = kv.w;
            *(float4*)&Vs[row*ATS + c4] = vv;
        }
        __syncthreads();   // tiles ready

        // scores: s[i][j] = sum_d Qs[ty4+i][d] * KT[d][tx4+j]   (d ascending)
        float s[4][4];
        #pragma unroll
        for (int i = 0; i < 4; i++)
            #pragma unroll
            for (int j = 0; j < 4; j++) s[i][j] = 0.f;
        #pragma unroll
        for (int dq = 0; dq < 16; dq++) {
            const int d0 = dq*4;
            float4 a0 = *(const float4*)&Qs[(ty*4+0)*ATS + d0];
            float4 a1 = *(const float4*)&Qs[(ty*4+1)*ATS + d0];
            float4 a2 = *(const float4*)&Qs[(ty*4+2)*ATS + d0];
            float4 a3 = *(const float4*)&Qs[(ty*4+3)*ATS + d0];
            float4 k0 = *(const float4*)&KT[(d0+0)*ATS + tx*4];
            float4 k1 = *(const float4*)&KT[(d0+1)*ATS + tx*4];
            float4 k2 = *(const float4*)&KT[(d0+2)*ATS + tx*4];
            float4 k3 = *(const float4*)&KT[(d0+3)*ATS + tx*4];
            #pragma unroll
            for (int i = 0; i < 4; i++) {
                float4 a = (i==0)?a0:(i==1)?a1:(i==2)?a2:a3;
                s[i][0] = fmaf(a.x, k0.x, s[i][0]); s[i][1] = fmaf(a.x, k0.y, s[i][1]);
                s[i][2] = fmaf(a.x, k0.z, s[i][2]); s[i][3] = fmaf(a.x, k0.w, s[i][3]);
                s[i][0] = fmaf(a.y, k1.x, s[i][0]); s[i][1] = fmaf(a.y, k1.y, s[i][1]);
                s[i][2] = fmaf(a.y, k1.z, s[i][2]); s[i][3] = fmaf(a.y, k1.w, s[i][3]);
                s[i][0] = fmaf(a.z, k2.x, s[i][0]); s[i][1] = fmaf(a.z, k2.y, s[i][1]);
                s[i][2] = fmaf(a.z, k2.z, s[i][2]); s[i][3] = fmaf(a.z, k2.w, s[i][3]);
                s[i][0] = fmaf(a.w, k3.x, s[i][0]); s[i][1] = fmaf(a.w, k3.y, s[i][1]);
                s[i][2] = fmaf(a.w, k3.z, s[i][2]); s[i][3] = fmaf(a.w, k3.w, s[i][3]);
            }
        }
        // key mask: position >= SEQ -> += NEG
        int kst = kb*64 + tx*4;
        #pragma unroll
        for (int j = 0; j < 4; j++) {
            if (kst + j >= SEQ) {
                #pragma unroll
                for (int i = 0; i < 4; i++) s[i][j] += NEGV;
            }
        }
        // online softmax update
        float al[4];
        #pragma unroll
        for (int i = 0; i < 4; i++) {
            float m = fmaxf(fmaxf(s[i][0], s[i][1]), fmaxf(s[i][2], s[i][3]));
            #pragma unroll
            for (int o = 8; o > 0; o >>= 1)
                m = fmaxf(m, __shfl_xor_sync(0xffffffffu, m, o));
            float nm = fmaxf(Mr[i], m);
            al[i] = expf(Mr[i] - nm);
            Mr[i] = nm;
            float p0 = expf(s[i][0] - nm);
            float p1 = expf(s[i][1] - nm);
            float p2 = expf(s[i][2] - nm);
            float p3 = expf(s[i][3] - nm);
            *(float4*)&Ps[(ty*4+i)*ATS + tx*4] = make_float4(p0, p1, p2, p3);
            float rsum = p0 + p1 + p2 + p3;
            #pragma unroll
            for (int o = 8; o > 0; o >>= 1)
                rsum += __shfl_xor_sync(0xffffffffu, rsum, o);
            Lr[i] = Lr[i]*al[i] + rsum;
        }
        __syncthreads();   // Ps visible
        // PV: acc[i][j] += sum_k Ps[ty4+i][k] * Vs[k][tx4+j]   (k ascending)
        #pragma unroll
        for (int i = 0; i < 4; i++)
            #pragma unroll
            for (int j = 0; j < 4; j++) acc[i][j] *= al[i];
        #pragma unroll
        for (int kq = 0; kq < 16; kq++) {
            const int k0i = kq*4;
            float4 p0 = *(const float4*)&Ps[(ty*4+0)*ATS + k0i];
            float4 p1 = *(const float4*)&Ps[(ty*4+1)*ATS + k0i];
            float4 p2 = *(const float4*)&Ps[(ty*4+2)*ATS + k0i];
            float4 p3 = *(const float4*)&Ps[(ty*4+3)*ATS + k0i];
            float4 v0 = *(const float4*)&Vs[(k0i+0)*ATS + tx*4];
            float4 v1 = *(const float4*)&Vs[(k0i+1)*ATS + tx*4];
            float4 v2 = *(const float4*)&Vs[(k0i+2)*ATS + tx*4];
            float4 v3 = *(const float4*)&Vs[(k0i+3)*ATS + tx*4];
            #pragma unroll
            for (int i = 0; i < 4; i++) {
                float4 p = (i==0)?p0:(i==1)?p1:(i==2)?p2:p3;
                acc[i][0] = fmaf(p.x, v0.x, acc[i][0]); acc[i][1] = fmaf(p.x, v0.y, acc[i][1]);
                acc[i][2] = fmaf(p.x, v0.z, acc[i][2]); acc[i][3] = fmaf(p.x, v0.w, acc[i][3]);
                acc[i][0] = fmaf(p.y, v1.x, acc[i][0]); acc[i][1] = fmaf(p.y, v1.y, acc[i][1]);
                acc[i][2] = fmaf(p.y, v1.z, acc[i][2]); acc[i][3] = fmaf(p.y, v1.w, acc[i][3]);
                acc[i][0] = fmaf(p.z, v2.x, acc[i][0]); acc[i][1] = fmaf(p.z, v2.y, acc[i][1]);
                acc[i][2] = fmaf(p.z, v2.z, acc[i][2]); acc[i][3] = fmaf(p.z, v2.w, acc[i][3]);
                acc[i][0] = fmaf(p.w, v3.x, acc[i][0]); acc[i][1] = fmaf(p.w, v3.y, acc[i][1]);
                acc[i][2] = fmaf(p.w, v3.z, acc[i][2]); acc[i][3] = fmaf(p.w, v3.w, acc[i][3]);
            }
        }
    }

    float* obase = ctx + ((size_t)(b*SEQP + qb*64))*DM + h*HD;
    #pragma unroll
    for (int i = 0; i < 4; i++) {
        float inv = 1.f / Lr[i];
        *(float4*)(obase + (size_t)(ty*4+i)*DM + tx*4) =
            make_float4(acc[i][0]*inv, acc[i][1]*inv, acc[i][2]*inv, acc[i][3]*inv);
    }
}

// ---------------- host orchestration ----------------
extern "C" void kernel_launch(void* const* d_in, const int* in_sizes, int n_in,
                              void* d_out, int out_size)
{
    const float* pixel   = (const float*)d_in[0];
    const float* patch_w = (const float*)d_in[1];
    const float* patch_b = (const float*)d_in[2];
    const float* cls     = (const float*)d_in[3];
    const float* pos     = (const float*)d_in[4];
    const float* Wq      = (const float*)d_in[5];
    const float* bq      = (const float*)d_in[6];
    const float* Wk      = (const float*)d_in[7];
    const float* bk      = (const float*)d_in[8];
    const float* Wv      = (const float*)d_in[9];
    const float* bv      = (const float*)d_in[10];
    const float* Wo      = (const float*)d_in[11];
    const float* bo      = (const float*)d_in[12];
    const float* ln1g    = (const float*)d_in[13];
    const float* ln1b    = (const float*)d_in[14];
    const float* ln2g    = (const float*)d_in[15];
    const float* ln2b    = (const float*)d_in[16];
    const float* fw1     = (const float*)d_in[17];
    const float* fb1     = (const float*)d_in[18];
    const float* fw2     = (const float*)d_in[19];
    const float* fb2     = (const float*)d_in[20];
    const float* ng      = (const float*)d_in[21];
    const float* nbias   = (const float*)d_in[22];
    const int*   rnd     = (const int*)d_in[23];
    float* out = (float*)d_out;

    float *pPatch, *pX, *pXp, *pQ, *pK, *pV, *pCtx, *pXn2, *pFfh;
    cudaGetSymbolAddress((void**)&pPatch, g_patches);
    cudaGetSymbolAddress((void**)&pX,   g_X);
    cudaGetSymbolAddress((void**)&pXp,  g_xp);
    cudaGetSymbolAddress((void**)&pQ,   g_Q);
    cudaGetSymbolAddress((void**)&pK,   g_K);
    cudaGetSymbolAddress((void**)&pV,   g_V);
    cudaGetSymbolAddress((void**)&pCtx, g_ctx);
    cudaGetSymbolAddress((void**)&pXn2, g_xn2);
    cudaGetSymbolAddress((void**)&pFfh, g_ffh);

    const int attn_smem = 4*64*ATS*(int)sizeof(float);  // 69632 B
    cudaFuncSetAttribute(attn_kernel, cudaFuncAttributeMaxDynamicSharedMemorySize, attn_smem);

    // ---- patch embedding ----
    patch_gather<<<cdiv(2*1024*DM, 256), 256>>>(pixel, pPatch);
    gemm_tf32<<<dim3(DM/GBN, cdiv(2048, GBM)), 256>>>(pPatch, patch_w, patch_b, pCtx,
                                                      2048, DM, DM, 0, 2048, 2048);
    assemble_embed<<<cdiv(2*SEQ*DM, 256), 256>>>(pCtx, cls, pos, pX);

    for (int l = 0; l < NLAY; l++) {
        const size_t wo = (size_t)l*DM*DM;
        // LN1 -> padded (zeros in pad rows)
        ln_kernel<<<2*SEQP, 256>>>(pX, ln1g + l*DM, ln1b + l*DM, pXp, SEQ, SEQP);
        // merged QKV projection (tf32 MMA)
        gemm_qkv<<<dim3(3*DM/GBN, cdiv(2*SEQP, GBM)), 256>>>(pXp,
                                                             Wq + wo, Wk + wo, Wv + wo,
                                                             bq + l*DM, bk + l*DM, bv + l*DM,
                                                             pQ, pK, pV, 2*SEQP, DM);
        // sparse attention (fp32, vectorized)
        attn_kernel<<<dim3(NBLK, NH, 2), 256, attn_smem>>>(pQ, pK, pV, rnd, pCtx);
        // output projection: single launch over both batches, row-remapped accumulate
        gemm_tf32<<<dim3(DM/GBN, cdiv(2*SEQP, GBM)), 256>>>(pCtx, Wo + wo, bo + l*DM, pX,
                                                            2*SEQP, DM, DM, 1, SEQP, SEQ);
        // LN2 + FFN
        ln_kernel<<<2*SEQ, 256>>>(pX, ln2g + l*DM, ln2b + l*DM, pXn2, SEQ, SEQ);
        gemm_tf32<<<dim3(DFF/GBN, cdiv(2*SEQ, GBM)), 256>>>(pXn2, fw1 + (size_t)l*DM*DFF,
                                                            fb1 + l*DFF, pFfh,
                                                            2*SEQ, DFF, DM, 2, 2*SEQ, 2*SEQ);
        gemm_tf32<<<dim3(DM/GBN, cdiv(2*SEQ, GBM)), 256>>>(pFfh, fw2 + (size_t)l*DFF*DM,
                                                           fb2 + l*DM, pX,
                                                           2*SEQ, DM, DFF, 1, 2*SEQ, 2*SEQ);
    }
    // final layernorm straight into d_out
    ln_kernel<<<2*SEQ, 256>>>(pX, ng, nbias, out, SEQ, SEQ);
}

// round 16
// speedup vs baseline: 1.0294x; 1.0035x over previous
#include <cuda_runtime.h>

#define SEQ   1025
#define SEQP  1088
#define NBLK  17
#define DM    768
#define DFF   3072
#define NH    12
#define HD    64
#define NLAY  12
#define NEGV  (-10000.0f)

// ---------------- scratch (no allocation allowed) ----------------
__device__ float g_patches[2*1024*DM];
__device__ float g_X   [2*SEQ *DM];
__device__ float g_xp  [2*SEQP*DM];
__device__ float g_Q   [2*SEQP*DM];
__device__ float g_K   [2*SEQP*DM];
__device__ float g_V   [2*SEQP*DM];
__device__ float g_ctx [2*SEQP*DM];
__device__ float g_xn2 [2*SEQ *DM];
__device__ float g_ffh [2*SEQ *DFF];

static inline int cdiv(int a, int b) { return (a + b - 1) / b; }

// ---------------- patch gather ----------------
__global__ void patch_gather(const float* __restrict__ px, float* __restrict__ out)
{
    int idx = blockIdx.x * blockDim.x + threadIdx.x;
    if (idx >= 2*1024*DM) return;
    int j  = idx % DM;
    int p  = (idx / DM) % 1024;
    int b  = idx / (DM * 1024);
    int c  = j >> 8;
    int py = (j >> 4) & 15;
    int pxl= j & 15;
    int gy = p >> 5;
    int gx = p & 31;
    out[idx] = px[(((size_t)b*3 + c)*512 + gy*16 + py)*512 + gx*16 + pxl];
}

// ---------------- embedding assemble ----------------
__global__ void assemble_embed(const float* __restrict__ tmp, const float* __restrict__ cls,
                               const float* __restrict__ pos, float* __restrict__ X)
{
    int idx = blockIdx.x * blockDim.x + threadIdx.x;
    if (idx >= 2*SEQ*DM) return;
    int d = idx % DM;
    int s = (idx / DM) % SEQ;
    int b = idx / (DM * SEQ);
    float v = (s == 0) ? cls[d] : tmp[((size_t)b*1024 + (s-1))*DM + d];
    X[idx] = v + pos[(size_t)s*DM + d];
}

// ---------------- layernorm (block per row), zero-pads rows >= rows_in ----------------
__global__ __launch_bounds__(256) void ln_kernel(const float* __restrict__ X,
                                                 const float* __restrict__ gam,
                                                 const float* __restrict__ bet,
                                                 float* __restrict__ Y,
                                                 int rows_in, int rows_out)
{
    __shared__ float redS[8];
    __shared__ float redQ[8];
    int r = blockIdx.x;
    int b = r / rows_out;
    int s = r % rows_out;
    int t = threadIdx.x;
    float* y = Y + (size_t)r * DM;
    if (s >= rows_in) {
        y[t] = 0.f; y[t+256] = 0.f; y[t+512] = 0.f;
        return;
    }
    const float* x = X + ((size_t)b*rows_in + s)*DM;
    float x0 = x[t], x1 = x[t+256], x2 = x[t+512];
    float sm = x0 + x1 + x2;
    float sq = x0*x0 + x1*x1 + x2*x2;
    #pragma unroll
    for (int o = 16; o > 0; o >>= 1) {
        sm += __shfl_xor_sync(0xffffffffu, sm, o);
        sq += __shfl_xor_sync(0xffffffffu, sq, o);
    }
    if ((t & 31) == 0) { redS[t >> 5] = sm; redQ[t >> 5] = sq; }
    __syncthreads();
    float ts = 0.f, tq = 0.f;
    #pragma unroll
    for (int w = 0; w < 8; w++) { ts += redS[w]; tq += redQ[w]; }
    float mean = ts * (1.f/768.f);
    float var  = tq * (1.f/768.f) - mean*mean;
    float inv  = rsqrtf(var + 1e-5f);
    y[t]     = (x0 - mean)*inv*gam[t]     + bet[t];
    y[t+256] = (x1 - mean)*inv*gam[t+256] + bet[t+256];
    y[t+512] = (x2 - mean)*inv*gam[t+512] + bet[t+512];
}

// ---------------- tf32 helpers ----------------
__device__ __forceinline__ unsigned f2tf(float x) {
    unsigned r;
    asm("cvt.rna.tf32.f32 %0, %1;" : "=r"(r) : "f"(x));
    return r;
}

__device__ __forceinline__ void mma_tf32(float* d, const unsigned* a, const unsigned* b) {
    asm volatile(
        "mma.sync.aligned.m16n8k8.row.col.f32.tf32.tf32.f32 "
        "{%0,%1,%2,%3}, {%4,%5,%6,%7}, {%8,%9}, {%0,%1,%2,%3};"
        : "+f"(d[0]), "+f"(d[1]), "+f"(d[2]), "+f"(d[3])
        : "r"(a[0]), "r"(a[1]), "r"(a[2]), "r"(a[3]), "r"(b[0]), "r"(b[1]));
}

// ---------------- tf32 tensor-core GEMM core (double-buffered, 128x128 tile) ----------------
#define GBM 128
#define GBN 128
#define GAS 20    // As row stride (floats)
#define GBS 136   // Bs row stride (floats) -- 136 % 32 == 8 for perfect banks
#define ASZ (GBM*GAS)
#define BSZ (16*GBS)

__device__ __forceinline__ void gemm_body(const float* __restrict__ A,
                                          const float* __restrict__ W,
                                          const float* __restrict__ bias,
                                          float* __restrict__ C,
                                          int M, int N, int K, int flags,
                                          int rows_in_pb, int rows_out_pb,
                                          int row0, int col0,
                                          unsigned* As, unsigned* Bs)
{
    const int tid = threadIdx.x;
    const int w = tid >> 5, l = tid & 31;
    const int wm = w >> 2, wn = w & 3;        // 2 x 4 warp grid
    const int g = l >> 2, t = l & 3;

    const int arow = tid >> 1;           // 0..127
    const int acol = (tid & 1) * 8;      // 0 or 8
    const int brow = tid >> 4;           // 0..15
    const int bcol = (tid & 15) * 8;     // 0..120

    const int argl = row0 + arow;
    const bool avalid = argl < M;
    const float* Ap = avalid ? (A + (size_t)argl*K + acol) : A;
    const float* Wp = W + (size_t)brow*N + col0 + bcol;

    float4 av0 = avalid ? *(const float4*)(Ap)     : make_float4(0.f,0.f,0.f,0.f);
    float4 av1 = avalid ? *(const float4*)(Ap + 4) : make_float4(0.f,0.f,0.f,0.f);
    float4 bv0 = *(const float4*)(Wp);
    float4 bv1 = *(const float4*)(Wp + 4);
    {
        uint4 u0 = make_uint4(f2tf(av0.x), f2tf(av0.y), f2tf(av0.z), f2tf(av0.w));
        uint4 u1 = make_uint4(f2tf(av1.x), f2tf(av1.y), f2tf(av1.z), f2tf(av1.w));
        *(uint4*)&As[arow*GAS + acol]     = u0;
        *(uint4*)&As[arow*GAS + acol + 4] = u1;
        uint4 w0 = make_uint4(f2tf(bv0.x), f2tf(bv0.y), f2tf(bv0.z), f2tf(bv0.w));
        uint4 w1 = make_uint4(f2tf(bv1.x), f2tf(bv1.y), f2tf(bv1.z), f2tf(bv1.w));
        *(uint4*)&Bs[brow*GBS + bcol]     = w0;
        *(uint4*)&Bs[brow*GBS + bcol + 4] = w1;
    }
    __syncthreads();

    float acc[4][4][4];
    #pragma unroll
    for (int mt = 0; mt < 4; mt++)
        #pragma unroll
        for (int nt = 0; nt < 4; nt++)
            #pragma unroll
            for (int i = 0; i < 4; i++) acc[mt][nt][i] = 0.f;

    int cur = 0;
    for (int k0 = 0; k0 < K; k0 += 16) {
        const bool more = (k0 + 16 < K);
        if (more) {
            av0 = avalid ? *(const float4*)(Ap + k0 + 16)     : make_float4(0.f,0.f,0.f,0.f);
            av1 = avalid ? *(const float4*)(Ap + k0 + 16 + 4) : make_float4(0.f,0.f,0.f,0.f);
            bv0 = *(const float4*)(Wp + (size_t)(k0 + 16)*N);
            bv1 = *(const float4*)(Wp + (size_t)(k0 + 16)*N + 4);
        }

        const unsigned* Ab = As + cur*ASZ;
        const unsigned* Bb = Bs + cur*BSZ;
        #pragma unroll
        for (int kh = 0; kh < 2; kh++) {
            const int kb = kh * 8;
            unsigned af[4][4], bf[4][2];
            #pragma unroll
            for (int mt = 0; mt < 4; mt++) {
                int r = wm*64 + mt*16;
                af[mt][0] = Ab[(r+g)  *GAS + kb + t];
                af[mt][1] = Ab[(r+g+8)*GAS + kb + t];
                af[mt][2] = Ab[(r+g)  *GAS + kb + t + 4];
                af[mt][3] = Ab[(r+g+8)*GAS + kb + t + 4];
            }
            #pragma unroll
            for (int nt = 0; nt < 4; nt++) {
                int c = wn*32 + nt*8 + g;
                bf[nt][0] = Bb[(kb+t)  *GBS + c];
                bf[nt][1] = Bb[(kb+t+4)*GBS + c];
            }
            #pragma unroll
            for (int mt = 0; mt < 4; mt++)
                #pragma unroll
                for (int nt = 0; nt < 4; nt++)
                    mma_tf32(acc[mt][nt], af[mt], bf[nt]);
        }

        if (more) {
            unsigned* An = As + (cur^1)*ASZ;
            unsigned* Bn = Bs + (cur^1)*BSZ;
            uint4 u0 = make_uint4(f2tf(av0.x), f2tf(av0.y), f2tf(av0.z), f2tf(av0.w));
            uint4 u1 = make_uint4(f2tf(av1.x), f2tf(av1.y), f2tf(av1.z), f2tf(av1.w));
            *(uint4*)&An[arow*GAS + acol]     = u0;
            *(uint4*)&An[arow*GAS + acol + 4] = u1;
            uint4 w0 = make_uint4(f2tf(bv0.x), f2tf(bv0.y), f2tf(bv0.z), f2tf(bv0.w));
            uint4 w1 = make_uint4(f2tf(bv1.x), f2tf(bv1.y), f2tf(bv1.z), f2tf(bv1.w));
            *(uint4*)&Bn[brow*GBS + bcol]     = w0;
            *(uint4*)&Bn[brow*GBS + bcol + 4] = w1;
            __syncthreads();
            cur ^= 1;
        }
    }

    // epilogue
    #pragma unroll
    for (int mt = 0; mt < 4; mt++) {
        #pragma unroll
        for (int half = 0; half < 2; half++) {
            int rl = wm*64 + mt*16 + g + half*8;
            int r  = row0 + rl;
            if (r < M) {
                int bidx = r / rows_in_pb;
                int s    = r - bidx * rows_in_pb;
                if (s < rows_out_pb) {
                    float* crow = C + ((size_t)bidx*rows_out_pb + s)*N + col0;
                    #pragma unroll
                    for (int nt = 0; nt < 4; nt++) {
                        int c = wn*32 + nt*8 + 2*t;
                        float v0 = acc[mt][nt][half*2+0] + bias[col0 + c];
                        float v1 = acc[mt][nt][half*2+1] + bias[col0 + c + 1];
                        if (flags & 2) {
                            v0 = 0.5f * v0 * (1.0f + erff(v0 * 0.70710678118654752f));
                            v1 = 0.5f * v1 * (1.0f + erff(v1 * 0.70710678118654752f));
                        }
                        if (flags & 1) {
                            float2 old = *(const float2*)(crow + c);
                            v0 += old.x; v1 += old.y;
                        }
                        *(float2*)(crow + c) = make_float2(v0, v1);
                    }
                }
            }
        }
    }
}

__global__ __launch_bounds__(256, 2) void gemm_tf32(const float* __restrict__ A,
                                                    const float* __restrict__ W,
                                                    const float* __restrict__ bias,
                                                    float* __restrict__ C,
                                                    int M, int N, int K, int flags,
                                                    int rows_in_pb, int rows_out_pb)
{
    __shared__ unsigned As[2*ASZ];
    __shared__ unsigned Bs[2*BSZ];
    gemm_body(A, W, bias, C, M, N, K, flags, rows_in_pb, rows_out_pb,
              blockIdx.y * GBM, blockIdx.x * GBN, As, Bs);
}

// merged QKV: grid.x = 3*(DM/GBN) = 18; sel picks the weight/bias/output set.
__global__ __launch_bounds__(256, 2) void gemm_qkv(const float* __restrict__ A,
                                                   const float* __restrict__ Wq,
                                                   const float* __restrict__ Wk,
                                                   const float* __restrict__ Wv,
                                                   const float* __restrict__ bq,
                                                   const float* __restrict__ bk,
                                                   const float* __restrict__ bv,
                                                   float* __restrict__ Q,
                                                   float* __restrict__ Kout,
                                                   float* __restrict__ V,
                                                   int M, int Kdim)
{
    __shared__ unsigned As[2*ASZ];
    __shared__ unsigned Bs[2*BSZ];
    const int blocks_per = DM / GBN;      // 6
    const int sel  = blockIdx.x / blocks_per;
    const int col0 = (blockIdx.x - sel * blocks_per) * GBN;
    const float* W = (sel == 0) ? Wq : (sel == 1) ? Wk : Wv;
    const float* b = (sel == 0) ? bq : (sel == 1) ? bk : bv;
    float*       C = (sel == 0) ? Q  : (sel == 1) ? Kout : V;
    gemm_body(A, W, b, C, M, DM, Kdim, 0, M, M,
              blockIdx.y * GBM, col0, As, Bs);
}

// ---------------- BigBird sparse attention (fp32, online softmax) ----------------
// Vectorized smem: Q[row][d] s68, KT[d][key] s68 (transposed), V[k][d] s68,
// P[row][k] s68. All inner-loop smem traffic is LDS.128 / STS.128, conflict-free.
#define ATS 68
__global__ __launch_bounds__(256) void attn_kernel(const float* __restrict__ Qg,
                                                   const float* __restrict__ Kg,
                                                   const float* __restrict__ Vg,
                                                   const int*   __restrict__ rnd,
                                                   float* __restrict__ ctx)
{
    extern __shared__ float smem[];
    float* Qs = smem;               // 64 x 68 (row, d)
    float* KT = smem + 64*ATS;      // 64 x 68 (d, key)  -- transposed
    float* Vs = smem + 2*64*ATS;    // 64 x 68 (k, d)
    float* Ps = smem + 3*64*ATS;    // 64 x 68 (row, k)

    const int qb  = blockIdx.x;
    const int h   = blockIdx.y;
    const int b   = blockIdx.z;
    const int tid = threadIdx.x;
    const int ty  = tid >> 4;
    const int tx  = tid & 15;

    int blist[17];
    int nb;
    if (qb == 0 || qb == NBLK-1) {
        nb = NBLK;
        #pragma unroll
        for (int i = 0; i < NBLK; i++) blist[i] = i;
    } else {
        const int* rp = rnd + ((size_t)h*15 + (qb-1))*3;
        int r0 = rp[0], r1 = rp[1], r2 = rp[2];
        if (qb == 1) {
            blist[0]=0; blist[1]=1; blist[2]=2; blist[3]=16;
            blist[4]=r0; blist[5]=r1; blist[6]=r2; nb = 7;
        } else if (qb == 15) {
            blist[0]=0; blist[1]=14; blist[2]=15; blist[3]=16;
            blist[4]=r0; blist[5]=r1; blist[6]=r2; nb = 7;
        } else {
            blist[0]=0; blist[1]=qb-1; blist[2]=qb; blist[3]=qb+1;
            blist[4]=r0; blist[5]=r1; blist[6]=r2; blist[7]=16; nb = 8;
        }
    }

    // load Q tile, pre-scaled by 1/sqrt(64)
    const float* qbase = Qg + ((size_t)(b*SEQP + qb*64))*DM + h*HD;
    #pragma unroll
    for (int it = 0; it < 4; it++) {
        int e = it*256 + tid;
        int row = e >> 4, c4 = (e & 15)*4;
        float4 v = *(const float4*)(qbase + (size_t)row*DM + c4);
        *(float4*)&Qs[row*ATS + c4] =
            make_float4(v.x*0.125f, v.y*0.125f, v.z*0.125f, v.w*0.125f);
    }

    float Mr[4], Lr[4], acc[4][4];
    #pragma unroll
    for (int i = 0; i < 4; i++) {
        Mr[i] = -1e30f; Lr[i] = 0.f;
        #pragma unroll
        for (int j = 0; j < 4; j++) acc[i][j] = 0.f;
    }

    for (int bi = 0; bi < nb; bi++) {
        int kb = blist[bi];
        const float* kbase = Kg + ((size_t)(b*SEQP + kb*64))*DM + h*HD;
        const float* vbase = Vg + ((size_t)(b*SEQP + kb*64))*DM + h*HD;
        __syncthreads();   // previous iter done reading KT/Vs/Ps; iter0: Qs stores done
        #pragma unroll
        for (int it = 0; it < 4; it++) {
            int e = it*256 + tid;
            int row = e >> 4, c4 = (e & 15)*4;   // row = key index, c4 = d quad
            float4 kv = *(const float4*)(kbase + (size_t)row*DM + c4);
            float4 vv = *(const float4*)(vbase + (size_t)row*DM + c4);
            // K transposed: KT[d][key]
            KT[(c4+0)*ATS + row] = kv.x;
            KT[(c4+1)*ATS + row] = kv.y;
            KT[(c4+2)*ATS + row] = kv.z;
            KT[(c4+3)*ATS + row] = kv.w;
            *(float4*)&Vs[row*ATS + c4] = vv;
        }
        __syncthreads();   // tiles ready

        // scores: s[i][j] = sum_d Qs[ty4+i][d] * KT[d][tx4+j]   (d ascending)
        float s[4][4];
        #pragma unroll
        for (int i = 0; i < 4; i++)
            #pragma unroll
            for (int j = 0; j < 4; j++) s[i][j] = 0.f;
        #pragma unroll
        for (int dq = 0; dq < 16; dq++) {
            const int d0 = dq*4;
            float4 a0 = *(const float4*)&Qs[(ty*4+0)*ATS + d0];
            float4 a1 = *(const float4*)&Qs[(ty*4+1)*ATS + d0];
            float4 a2 = *(const float4*)&Qs[(ty*4+2)*ATS + d0];
            float4 a3 = *(const float4*)&Qs[(ty*4+3)*ATS + d0];
            float4 k0 = *(const float4*)&KT[(d0+0)*ATS + tx*4];
            float4 k1 = *(const float4*)&KT[(d0+1)*ATS + tx*4];
            float4 k2 = *(const float4*)&KT[(d0+2)*ATS + tx*4];
            float4 k3 = *(const float4*)&KT[(d0+3)*ATS + tx*4];
            #pragma unroll
            for (int i = 0; i < 4; i++) {
                float4 a = (i==0)?a0:(i==1)?a1:(i==2)?a2:a3;
                s[i][0] = fmaf(a.x, k0.x, s[i][0]); s[i][1] = fmaf(a.x, k0.y, s[i][1]);
                s[i][2] = fmaf(a.x, k0.z, s[i][2]); s[i][3] = fmaf(a.x, k0.w, s[i][3]);
                s[i][0] = fmaf(a.y, k1.x, s[i][0]); s[i][1] = fmaf(a.y, k1.y, s[i][1]);
                s[i][2] = fmaf(a.y, k1.z, s[i][2]); s[i][3] = fmaf(a.y, k1.w, s[i][3]);
                s[i][0] = fmaf(a.z, k2.x, s[i][0]); s[i][1] = fmaf(a.z, k2.y, s[i][1]);
                s[i][2] = fmaf(a.z, k2.z, s[i][2]); s[i][3] = fmaf(a.z, k2.w, s[i][3]);
                s[i][0] = fmaf(a.w, k3.x, s[i][0]); s[i][1] = fmaf(a.w, k3.y, s[i][1]);
                s[i][2] = fmaf(a.w, k3.z, s[i][2]); s[i][3] = fmaf(a.w, k3.w, s[i][3]);
            }
        }
        // key mask: position >= SEQ -> += NEG
        int kst = kb*64 + tx*4;
        #pragma unroll
        for (int j = 0; j < 4; j++) {
            if (kst + j >= SEQ) {
                #pragma unroll
                for (int i = 0; i < 4; i++) s[i][j] += NEGV;
            }
        }
        // online softmax update
        float al[4];
        #pragma unroll
        for (int i = 0; i < 4; i++) {
            float m = fmaxf(fmaxf(s[i][0], s[i][1]), fmaxf(s[i][2], s[i][3]));
            #pragma unroll
            for (int o = 8; o > 0; o >>= 1)
                m = fmaxf(m, __shfl_xor_sync(0xffffffffu, m, o));
            float nm = fmaxf(Mr[i], m);
            al[i] = expf(Mr[i] - nm);
            Mr[i] = nm;
            float p0 = expf(s[i][0] - nm);
            float p1 = expf(s[i][1] - nm);
            float p2 = expf(s[i][2] - nm);
            float p3 = expf(s[i][3] - nm);
            *(float4*)&Ps[(ty*4+i)*ATS + tx*4] = make_float4(p0, p1, p2, p3);
            float rsum = p0 + p1 + p2 + p3;
            #pragma unroll
            for (int o = 8; o > 0; o >>= 1)
                rsum += __shfl_xor_sync(0xffffffffu, rsum, o);
            Lr[i] = Lr[i]*al[i] + rsum;
        }
        __syncthreads();   // Ps visible
        // PV: acc[i][j] += sum_k Ps[ty4+i][k] * Vs[k][tx4+j]   (k ascending)
        #pragma unroll
        for (int i = 0; i < 4; i++)
            #pragma unroll
            for (int j = 0; j < 4; j++) acc[i][j] *= al[i];
        #pragma unroll
        for (int kq = 0; kq < 16; kq++) {
            const int k0i = kq*4;
            float4 p0 = *(const float4*)&Ps[(ty*4+0)*ATS + k0i];
            float4 p1 = *(const float4*)&Ps[(ty*4+1)*ATS + k0i];
            float4 p2 = *(const float4*)&Ps[(ty*4+2)*ATS + k0i];
            float4 p3 = *(const float4*)&Ps[(ty*4+3)*ATS + k0i];
            float4 v0 = *(const float4*)&Vs[(k0i+0)*ATS + tx*4];
            float4 v1 = *(const float4*)&Vs[(k0i+1)*ATS + tx*4];
            float4 v2 = *(const float4*)&Vs[(k0i+2)*ATS + tx*4];
            float4 v3 = *(const float4*)&Vs[(k0i+3)*ATS + tx*4];
            #pragma unroll
            for (int i = 0; i < 4; i++) {
                float4 p = (i==0)?p0:(i==1)?p1:(i==2)?p2:p3;
                acc[i][0] = fmaf(p.x, v0.x, acc[i][0]); acc[i][1] = fmaf(p.x, v0.y, acc[i][1]);
                acc[i][2] = fmaf(p.x, v0.z, acc[i][2]); acc[i][3] = fmaf(p.x, v0.w, acc[i][3]);
                acc[i][0] = fmaf(p.y, v1.x, acc[i][0]); acc[i][1] = fmaf(p.y, v1.y, acc[i][1]);
                acc[i][2] = fmaf(p.y, v1.z, acc[i][2]); acc[i][3] = fmaf(p.y, v1.w, acc[i][3]);
                acc[i][0] = fmaf(p.z, v2.x, acc[i][0]); acc[i][1] = fmaf(p.z, v2.y, acc[i][1]);
                acc[i][2] = fmaf(p.z, v2.z, acc[i][2]); acc[i][3] = fmaf(p.z, v2.w, acc[i][3]);
                acc[i][0] = fmaf(p.w, v3.x, acc[i][0]); acc[i][1] = fmaf(p.w, v3.y, acc[i][1]);
                acc[i][2] = fmaf(p.w, v3.z, acc[i][2]); acc[i][3] = fmaf(p.w, v3.w, acc[i][3]);
            }
        }
    }

    float* obase = ctx + ((size_t)(b*SEQP + qb*64))*DM + h*HD;
    #pragma unroll
    for (int i = 0; i < 4; i++) {
        float inv = 1.f / Lr[i];
        *(float4*)(obase + (size_t)(ty*4+i)*DM + tx*4) =
            make_float4(acc[i][0]*inv, acc[i][1]*inv, acc[i][2]*inv, acc[i][3]*inv);
    }
}

// ---------------- host orchestration ----------------
extern "C" void kernel_launch(void* const* d_in, const int* in_sizes, int n_in,
                              void* d_out, int out_size)
{
    const float* pixel   = (const float*)d_in[0];
    const float* patch_w = (const float*)d_in[1];
    const float* patch_b = (const float*)d_in[2];
    const float* cls     = (const float*)d_in[3];
    const float* pos     = (const float*)d_in[4];
    const float* Wq      = (const float*)d_in[5];
    const float* bq      = (const float*)d_in[6];
    const float* Wk      = (const float*)d_in[7];
    const float* bk      = (const float*)d_in[8];
    const float* Wv      = (const float*)d_in[9];
    const float* bv      = (const float*)d_in[10];
    const float* Wo      = (const float*)d_in[11];
    const float* bo      = (const float*)d_in[12];
    const float* ln1g    = (const float*)d_in[13];
    const float* ln1b    = (const float*)d_in[14];
    const float* ln2g    = (const float*)d_in[15];
    const float* ln2b    = (const float*)d_in[16];
    const float* fw1     = (const float*)d_in[17];
    const float* fb1     = (const float*)d_in[18];
    const float* fw2     = (const float*)d_in[19];
    const float* fb2     = (const float*)d_in[20];
    const float* ng      = (const float*)d_in[21];
    const float* nbias   = (const float*)d_in[22];
    const int*   rnd     = (const int*)d_in[23];
    float* out = (float*)d_out;

    float *pPatch, *pX, *pXp, *pQ, *pK, *pV, *pCtx, *pXn2, *pFfh;
    cudaGetSymbolAddress((void**)&pPatch, g_patches);
    cudaGetSymbolAddress((void**)&pX,   g_X);
    cudaGetSymbolAddress((void**)&pXp,  g_xp);
    cudaGetSymbolAddress((void**)&pQ,   g_Q);
    cudaGetSymbolAddress((void**)&pK,   g_K);
    cudaGetSymbolAddress((void**)&pV,   g_V);
    cudaGetSymbolAddress((void**)&pCtx, g_ctx);
    cudaGetSymbolAddress((void**)&pXn2, g_xn2);
    cudaGetSymbolAddress((void**)&pFfh, g_ffh);

    const int attn_smem = 4*64*ATS*(int)sizeof(float);  // 69632 B
    cudaFuncSetAttribute(attn_kernel, cudaFuncAttributeMaxDynamicSharedMemorySize, attn_smem);

    // ---- patch embedding ----
    patch_gather<<<cdiv(2*1024*DM, 256), 256>>>(pixel, pPatch);
    gemm_tf32<<<dim3(DM/GBN, cdiv(2048, GBM)), 256>>>(pPatch, patch_w, patch_b, pCtx,
                                                      2048, DM, DM, 0, 2048, 2048);
    assemble_embed<<<cdiv(2*SEQ*DM, 256), 256>>>(pCtx, cls, pos, pX);

    for (int l = 0; l < NLAY; l++) {
        const size_t wo = (size_t)l*DM*DM;
        // LN1 -> padded (zeros in pad rows)
        ln_kernel<<<2*SEQP, 256>>>(pX, ln1g + l*DM, ln1b + l*DM, pXp, SEQ, SEQP);
        // merged QKV projection (tf32 MMA)
        gemm_qkv<<<dim3(3*DM/GBN, cdiv(2*SEQP, GBM)), 256>>>(pXp,
                                                             Wq + wo, Wk + wo, Wv + wo,
                                                             bq + l*DM, bk + l*DM, bv + l*DM,
                                                             pQ, pK, pV, 2*SEQP, DM);
        // sparse attention (fp32, vectorized)
        attn_kernel<<<dim3(NBLK, NH, 2), 256, attn_smem>>>(pQ, pK, pV, rnd, pCtx);
        // output projection: single launch over both batches, row-remapped accumulate
        gemm_tf32<<<dim3(DM/GBN, cdiv(2*SEQP, GBM)), 256>>>(pCtx, Wo + wo, bo + l*DM, pX,
                                                            2*SEQP, DM, DM, 1, SEQP, SEQ);
        // LN2 + FFN
        ln_kernel<<<2*SEQ, 256>>>(pX, ln2g + l*DM, ln2b + l*DM, pXn2, SEQ, SEQ);
        gemm_tf32<<<dim3(DFF/GBN, cdiv(2*SEQ, GBM)), 256>>>(pXn2, fw1 + (size_t)l*DM*DFF,
                                                            fb1 + l*DFF, pFfh,
                                                            2*SEQ, DFF, DM, 2, 2*SEQ, 2*SEQ);
        gemm_tf32<<<dim3(DM/GBN, cdiv(2*SEQ, GBM)), 256>>>(pFfh, fw2 + (size_t)l*DFF*DM,
                                                           fb2 + l*DM, pX,
                                                           2*SEQ, DM, DFF, 1, 2*SEQ, 2*SEQ);
    }
    // final layernorm straight into d_out
    ln_kernel<<<2*SEQ, 256>>>(pX, ng, nbias, out, SEQ, SEQ);
}